// round 1
// baseline (speedup 1.0000x reference)
#include <cuda_runtime.h>
#include <math.h>

// Problem constants
constexpr int cB = 4;
constexpr int cS = 4096;
constexpr int cN = 256;
constexpr int cD = 1024;
constexpr int cG = 16;
constexpr int cC = 64;

// ---------------------------------------------------------------------------
// Scratch (static device allocations only; no cudaMalloc anywhere)
// ---------------------------------------------------------------------------
__device__ float g_nbuf[cB * cS * cD];   // normalized k / v (reused)
__device__ float g_k[cB * cS * cD];      // projected K
__device__ float g_v[cB * cS * cD];      // projected V
__device__ float g_nq[cB * cN * cD];     // normalized q
__device__ float g_q[cB * cN * cD];      // projected Q
__device__ float g_ao[cB * cN * cD];     // attention output
__device__ float g_p1[cB * cN * cD];     // parts after proj residual
__device__ float g_p2[cB * cN * cD];     // parts after reason residual
__device__ float g_t[cB * cN * cD];      // LN temp
__device__ float g_h[cB * cN * cD];      // MLP hidden
__device__ int   g_mask[cB * cS];
__device__ int   g_flag[1];

// ---------------------------------------------------------------------------
// Mask dtype detection: if the buffer is int32 0/1, all bytes at i%4!=0 are 0.
// If it is bool/uint8 (random 0/1), roughly half of them are 1.
// Scanning only B*S bytes is safe under either layout.
// ---------------------------------------------------------------------------
__global__ void detect_mask_kernel(const unsigned char* __restrict__ p, int* flag) {
    __shared__ int red[256];
    int t = threadIdx.x;
    int cnt = 0;
    for (int i = t; i < cB * cS; i += 256) {
        if ((i & 3) != 0 && p[i] != 0) cnt++;
    }
    red[t] = cnt;
    __syncthreads();
    for (int s = 128; s > 0; s >>= 1) {
        if (t < s) red[t] += red[t + s];
        __syncthreads();
    }
    if (t == 0) flag[0] = red[0];
}

__global__ void expand_mask_kernel(const void* __restrict__ p, const int* __restrict__ flag,
                                   int* __restrict__ mout) {
    int i = blockIdx.x * 256 + threadIdx.x;
    if (i >= cB * cS) return;
    int isbyte = flag[0] > 0;
    int v = isbyte ? (int)((const unsigned char*)p)[i] : ((const int*)p)[i];
    mout[i] = (v != 0) ? 1 : 0;
}

// ---------------------------------------------------------------------------
// LayerNorm over D=1024. addmode: 0=none, 1=elementwise add, 2=qpos broadcast
// ---------------------------------------------------------------------------
__global__ void ln_kernel(const float* __restrict__ x, const float* __restrict__ add,
                          int addmode, const float* __restrict__ w, const float* __restrict__ bias,
                          float* __restrict__ out) {
    __shared__ float row[cD];
    __shared__ float red[256];
    int r = blockIdx.x;
    int t = threadIdx.x;
    const float* xr = x + (size_t)r * cD;

    float lsum = 0.f;
    for (int i = t; i < cD; i += 256) {
        float v = xr[i];
        if (addmode == 1)      v += add[(size_t)r * cD + i];
        else if (addmode == 2) v += add[(size_t)r * cC + (i & (cC - 1))];
        row[i] = v;
        lsum += v;
    }
    red[t] = lsum;
    __syncthreads();
    for (int s = 128; s > 0; s >>= 1) {
        if (t < s) red[t] += red[t + s];
        __syncthreads();
    }
    float mu = red[0] * (1.f / cD);
    __syncthreads();

    float lvar = 0.f;
    for (int i = t; i < cD; i += 256) {
        float d = row[i] - mu;
        lvar += d * d;
    }
    red[t] = lvar;
    __syncthreads();
    for (int s = 128; s > 0; s >>= 1) {
        if (t < s) red[t] += red[t + s];
        __syncthreads();
    }
    float inv = rsqrtf(red[0] * (1.f / cD) + 1e-5f);
    for (int i = t; i < cD; i += 256) {
        out[(size_t)r * cD + i] = (row[i] - mu) * inv * w[i] + bias[i];
    }
}

// ---------------------------------------------------------------------------
// SGEMM  C[M,Nc] = A[M,K] @ W[Nc,K]^T (+bias)(+resid)
// BM=BN=128, BK=8, 256 threads, TM=TN=8. All dims assumed multiples of tile.
// ---------------------------------------------------------------------------
__global__ void __launch_bounds__(256) sgemm_nt(const float* __restrict__ A,
                                                const float* __restrict__ W,
                                                float* __restrict__ Cp,
                                                int M, int Nc, int K,
                                                const float* __restrict__ bias,
                                                const float* __restrict__ resid) {
    __shared__ float As[8][128];
    __shared__ float Bs[8][128];
    int t = threadIdx.x;
    int m0 = blockIdx.y * 128;
    int n0 = blockIdx.x * 128;

    int lrow = t >> 1;
    int lcol = (t & 1) * 4;
    const float* Ag = A + (size_t)(m0 + lrow) * K + lcol;
    const float* Wg = W + (size_t)(n0 + lrow) * K + lcol;

    int tx = t & 15;
    int ty = t >> 4;
    float acc[8][8];
#pragma unroll
    for (int i = 0; i < 8; i++)
#pragma unroll
        for (int j = 0; j < 8; j++) acc[i][j] = 0.f;

    for (int k0 = 0; k0 < K; k0 += 8) {
        float4 a4 = *(const float4*)(Ag + k0);
        float4 b4 = *(const float4*)(Wg + k0);
        As[lcol + 0][lrow] = a4.x; As[lcol + 1][lrow] = a4.y;
        As[lcol + 2][lrow] = a4.z; As[lcol + 3][lrow] = a4.w;
        Bs[lcol + 0][lrow] = b4.x; Bs[lcol + 1][lrow] = b4.y;
        Bs[lcol + 2][lrow] = b4.z; Bs[lcol + 3][lrow] = b4.w;
        __syncthreads();
#pragma unroll
        for (int k = 0; k < 8; k++) {
            float4 a0 = *(const float4*)&As[k][ty * 8];
            float4 a1 = *(const float4*)&As[k][ty * 8 + 4];
            float4 b0 = *(const float4*)&Bs[k][tx * 8];
            float4 b1 = *(const float4*)&Bs[k][tx * 8 + 4];
            float ar[8] = {a0.x, a0.y, a0.z, a0.w, a1.x, a1.y, a1.z, a1.w};
            float br[8] = {b0.x, b0.y, b0.z, b0.w, b1.x, b1.y, b1.z, b1.w};
#pragma unroll
            for (int i = 0; i < 8; i++)
#pragma unroll
                for (int j = 0; j < 8; j++) acc[i][j] += ar[i] * br[j];
        }
        __syncthreads();
    }

#pragma unroll
    for (int i = 0; i < 8; i++) {
        size_t row = (size_t)(m0 + ty * 8 + i);
        size_t base = row * Nc + n0 + tx * 8;
#pragma unroll
        for (int v = 0; v < 2; v++) {
            float4 o;
            o.x = acc[i][v * 4 + 0]; o.y = acc[i][v * 4 + 1];
            o.z = acc[i][v * 4 + 2]; o.w = acc[i][v * 4 + 3];
            if (bias) {
                const float4 bv = *(const float4*)&bias[n0 + tx * 8 + v * 4];
                o.x += bv.x; o.y += bv.y; o.z += bv.z; o.w += bv.w;
            }
            if (resid) {
                const float4 rv = *(const float4*)&resid[base + v * 4];
                o.x += rv.x; o.y += rv.y; o.z += rv.z; o.w += rv.w;
            }
            *(float4*)&Cp[base + v * 4] = o;
        }
    }
}

// ---------------------------------------------------------------------------
// Attention scores: attn[b,n,g,s] = scale * sum_c q[b,n,g,c] * k[b,s,g,c]
// grid: (S/128, N/128, B*G). Same tiling as sgemm_nt, K=C=64.
// ---------------------------------------------------------------------------
__global__ void __launch_bounds__(256) score_gemm(const float* __restrict__ q,
                                                  const float* __restrict__ k,
                                                  float* __restrict__ attn) {
    __shared__ float As[8][128];
    __shared__ float Bs[8][128];
    int z = blockIdx.z;
    int b = z / cG, g = z % cG;
    int t = threadIdx.x;
    int m0 = blockIdx.y * 128;   // n tile
    int n0 = blockIdx.x * 128;   // s tile

    int lrow = t >> 1;
    int lcol = (t & 1) * 4;
    const float* Ag = q + (size_t)(b * cN + m0 + lrow) * cD + g * cC + lcol;
    const float* Wg = k + (size_t)(b * cS + n0 + lrow) * cD + g * cC + lcol;

    int tx = t & 15;
    int ty = t >> 4;
    float acc[8][8];
#pragma unroll
    for (int i = 0; i < 8; i++)
#pragma unroll
        for (int j = 0; j < 8; j++) acc[i][j] = 0.f;

    for (int k0 = 0; k0 < cC; k0 += 8) {
        float4 a4 = *(const float4*)(Ag + k0);
        float4 b4 = *(const float4*)(Wg + k0);
        As[lcol + 0][lrow] = a4.x; As[lcol + 1][lrow] = a4.y;
        As[lcol + 2][lrow] = a4.z; As[lcol + 3][lrow] = a4.w;
        Bs[lcol + 0][lrow] = b4.x; Bs[lcol + 1][lrow] = b4.y;
        Bs[lcol + 2][lrow] = b4.z; Bs[lcol + 3][lrow] = b4.w;
        __syncthreads();
#pragma unroll
        for (int kk = 0; kk < 8; kk++) {
            float4 a0 = *(const float4*)&As[kk][ty * 8];
            float4 a1 = *(const float4*)&As[kk][ty * 8 + 4];
            float4 b0 = *(const float4*)&Bs[kk][tx * 8];
            float4 b1 = *(const float4*)&Bs[kk][tx * 8 + 4];
            float ar[8] = {a0.x, a0.y, a0.z, a0.w, a1.x, a1.y, a1.z, a1.w};
            float br[8] = {b0.x, b0.y, b0.z, b0.w, b1.x, b1.y, b1.z, b1.w};
#pragma unroll
            for (int i = 0; i < 8; i++)
#pragma unroll
                for (int j = 0; j < 8; j++) acc[i][j] += ar[i] * br[j];
        }
        __syncthreads();
    }

    const float scale = 0.125f;   // (D/G)^-0.5 = 64^-0.5
#pragma unroll
    for (int i = 0; i < 8; i++) {
        int n = m0 + ty * 8 + i;
        size_t base = (((size_t)b * cN + n) * cG + g) * cS + n0 + tx * 8;
#pragma unroll
        for (int v = 0; v < 2; v++) {
            float4 o;
            o.x = acc[i][v * 4 + 0] * scale; o.y = acc[i][v * 4 + 1] * scale;
            o.z = acc[i][v * 4 + 2] * scale; o.w = acc[i][v * 4 + 3] * scale;
            *(float4*)&attn[base + v * 4] = o;
        }
    }
}

// ---------------------------------------------------------------------------
// Masked softmax over S, one block per (b,n,g) row, in place.
// ---------------------------------------------------------------------------
__global__ void softmax_kernel(float* __restrict__ attn, const int* __restrict__ mask) {
    __shared__ float red[256];
    int r = blockIdx.x;                 // 0 .. B*N*G
    int t = threadIdx.x;
    int b = r / (cN * cG);
    float* rowp = attn + (size_t)r * cS;
    const int* mrow = mask + b * cS;

    float vals[16];
    int msk[16];
    float mx = -INFINITY;
#pragma unroll
    for (int i = 0; i < 16; i++) {
        int s = t + i * 256;
        msk[i] = mrow[s];
        vals[i] = rowp[s];
        if (!msk[i]) mx = fmaxf(mx, vals[i]);
    }
    red[t] = mx;
    __syncthreads();
    for (int s = 128; s > 0; s >>= 1) {
        if (t < s) red[t] = fmaxf(red[t], red[t + s]);
        __syncthreads();
    }
    mx = red[0];
    __syncthreads();

    float sum = 0.f;
#pragma unroll
    for (int i = 0; i < 16; i++) {
        float e = msk[i] ? 0.f : expf(vals[i] - mx);
        vals[i] = e;
        sum += e;
    }
    red[t] = sum;
    __syncthreads();
    for (int s = 128; s > 0; s >>= 1) {
        if (t < s) red[t] += red[t + s];
        __syncthreads();
    }
    float inv = (red[0] > 0.f) ? 1.f / red[0] : 0.f;
#pragma unroll
    for (int i = 0; i < 16; i++) {
        rowp[t + i * 256] = vals[i] * inv;
    }
}

// ---------------------------------------------------------------------------
// Generic NN GEMM: C = A[M,K] @ B[K,Nc] (+resid), batched via grid.z with
// split batch offsets: zo=z/zdiv, zi=z%zdiv; off = zo*x1 + zi*x2.
// BM=128, BN=64, BK=8, TM=8, TN=4, 256 threads.
// ---------------------------------------------------------------------------
__global__ void __launch_bounds__(256) gemm_nn(
    const float* __restrict__ A, int lda, int zdiv, long a1, long a2,
    const float* __restrict__ Bm, int ldb, long b1, long b2,
    float* __restrict__ Cp, int ldc, long c1, long c2,
    const float* __restrict__ resid, long r1, long r2,
    int M, int Nc, int K) {
    __shared__ float As[8][128];
    __shared__ float Bs[8][64];
    int z = blockIdx.z;
    int zo = z / zdiv, zi = z - zo * zdiv;
    const float* Ab = A + zo * a1 + zi * a2;
    const float* Bb = Bm + zo * b1 + zi * b2;
    float* Cb = Cp + zo * c1 + zi * c2;

    int t = threadIdx.x;
    int m0 = blockIdx.y * 128;
    int n0 = blockIdx.x * 64;

    int arow = t >> 1;
    int acol = (t & 1) * 4;
    const float* Ag = Ab + (size_t)(m0 + arow) * lda + acol;
    int bk = (t * 2) >> 6;
    int bn = (t * 2) & 63;
    const float* Bg = Bb + (size_t)bk * ldb + n0 + bn;

    int tx = t & 15;
    int ty = t >> 4;
    float acc[8][4];
#pragma unroll
    for (int i = 0; i < 8; i++)
#pragma unroll
        for (int j = 0; j < 4; j++) acc[i][j] = 0.f;

    for (int k0 = 0; k0 < K; k0 += 8) {
        float4 a4 = *(const float4*)(Ag + k0);
        As[acol + 0][arow] = a4.x; As[acol + 1][arow] = a4.y;
        As[acol + 2][arow] = a4.z; As[acol + 3][arow] = a4.w;
        float2 bv = *(const float2*)(Bg + (size_t)k0 * ldb);
        Bs[bk][bn] = bv.x; Bs[bk][bn + 1] = bv.y;
        __syncthreads();
#pragma unroll
        for (int kk = 0; kk < 8; kk++) {
            float4 a0 = *(const float4*)&As[kk][ty * 8];
            float4 a1v = *(const float4*)&As[kk][ty * 8 + 4];
            float4 bq = *(const float4*)&Bs[kk][tx * 4];
            float ar[8] = {a0.x, a0.y, a0.z, a0.w, a1v.x, a1v.y, a1v.z, a1v.w};
            float br[4] = {bq.x, bq.y, bq.z, bq.w};
#pragma unroll
            for (int i = 0; i < 8; i++)
#pragma unroll
                for (int j = 0; j < 4; j++) acc[i][j] += ar[i] * br[j];
        }
        __syncthreads();
    }

#pragma unroll
    for (int i = 0; i < 8; i++) {
        size_t row = (size_t)(m0 + ty * 8 + i);
        size_t off = row * ldc + n0 + tx * 4;
        float4 o;
        o.x = acc[i][0]; o.y = acc[i][1]; o.z = acc[i][2]; o.w = acc[i][3];
        if (resid) {
            const float4 rv = *(const float4*)&resid[zo * r1 + zi * r2 + off];
            o.x += rv.x; o.y += rv.y; o.z += rv.z; o.w += rv.w;
        }
        *(float4*)&Cb[off] = o;
    }
}

// ---------------------------------------------------------------------------
// Exact GELU: x * 0.5 * (1 + erf(x/sqrt(2)))
// ---------------------------------------------------------------------------
__global__ void gelu_kernel(float* __restrict__ x, int n) {
    int i = blockIdx.x * 256 + threadIdx.x;
    if (i >= n) return;
    float v = x[i];
    x[i] = 0.5f * v * (1.f + erff(v * 0.70710678118654752f));
}

// ---------------------------------------------------------------------------
// Host launcher
// ---------------------------------------------------------------------------
extern "C" void kernel_launch(void* const* d_in, const int* in_sizes, int n_in,
                              void* d_out, int out_size) {
    const float* feats   = (const float*)d_in[0];
    const float* parts   = (const float*)d_in[1];
    const float* qpos    = (const float*)d_in[2];
    const float* kpos    = (const float*)d_in[3];
    const void*  maskraw = d_in[4];
    const float* ln_q_w  = (const float*)d_in[5];
    const float* ln_q_b  = (const float*)d_in[6];
    const float* ln_k_w  = (const float*)d_in[7];
    const float* ln_k_b  = (const float*)d_in[8];
    const float* ln_v_w  = (const float*)d_in[9];
    const float* ln_v_b  = (const float*)d_in[10];
    const float* wq      = (const float*)d_in[11];
    const float* wk      = (const float*)d_in[12];
    const float* wv      = (const float*)d_in[13];
    const float* w_proj  = (const float*)d_in[14];
    const float* b_proj  = (const float*)d_in[15];
    const float* reason_ln_w = (const float*)d_in[16];
    const float* reason_ln_b = (const float*)d_in[17];
    const float* reason_w    = (const float*)d_in[18];
    const float* mlp_ln_w    = (const float*)d_in[19];
    const float* mlp_ln_b    = (const float*)d_in[20];
    const float* fc1_w   = (const float*)d_in[21];
    const float* fc1_b   = (const float*)d_in[22];
    const float* fc2_w   = (const float*)d_in[23];
    const float* fc2_b   = (const float*)d_in[24];

    float* out_parts = (float*)d_out;
    float* out_attn  = out_parts + (size_t)cB * cN * cD;

    float *p_nbuf, *p_k, *p_v, *p_nq, *p_q, *p_ao, *p_p1, *p_p2, *p_t, *p_h;
    int *p_mask, *p_flag;
    cudaGetSymbolAddress((void**)&p_nbuf, g_nbuf);
    cudaGetSymbolAddress((void**)&p_k, g_k);
    cudaGetSymbolAddress((void**)&p_v, g_v);
    cudaGetSymbolAddress((void**)&p_nq, g_nq);
    cudaGetSymbolAddress((void**)&p_q, g_q);
    cudaGetSymbolAddress((void**)&p_ao, g_ao);
    cudaGetSymbolAddress((void**)&p_p1, g_p1);
    cudaGetSymbolAddress((void**)&p_p2, g_p2);
    cudaGetSymbolAddress((void**)&p_t, g_t);
    cudaGetSymbolAddress((void**)&p_h, g_h);
    cudaGetSymbolAddress((void**)&p_mask, g_mask);
    cudaGetSymbolAddress((void**)&p_flag, g_flag);

    // Mask normalization
    detect_mask_kernel<<<1, 256>>>((const unsigned char*)maskraw, p_flag);
    expand_mask_kernel<<<(cB * cS + 255) / 256, 256>>>(maskraw, p_flag, p_mask);

    // Q path
    ln_kernel<<<cB * cN, 256>>>(parts, qpos, 2, ln_q_w, ln_q_b, p_nq);
    sgemm_nt<<<dim3(cD / 128, (cB * cN) / 128), 256>>>(p_nq, wq, p_q, cB * cN, cD, cD, nullptr, nullptr);

    // K path
    ln_kernel<<<cB * cS, 256>>>(feats, kpos, 1, ln_k_w, ln_k_b, p_nbuf);
    sgemm_nt<<<dim3(cD / 128, (cB * cS) / 128), 256>>>(p_nbuf, wk, p_k, cB * cS, cD, cD, nullptr, nullptr);

    // V path
    ln_kernel<<<cB * cS, 256>>>(feats, nullptr, 0, ln_v_w, ln_v_b, p_nbuf);
    sgemm_nt<<<dim3(cD / 128, (cB * cS) / 128), 256>>>(p_nbuf, wv, p_v, cB * cS, cD, cD, nullptr, nullptr);

    // Attention scores -> d_out attn region (pre-softmax), then softmax in place
    score_gemm<<<dim3(cS / 128, cN / 128, cB * cG), 256>>>(p_q, p_k, out_attn);
    softmax_kernel<<<cB * cN * cG, 256>>>(out_attn, p_mask);

    // AV: out[b,n,g,c] = sum_s attn[b,n,g,s] * v[b,s,g,c]
    gemm_nn<<<dim3(cC / 64, cN / 128, cB * cG), 256>>>(
        out_attn, cG * cS, cG, (long)cN * cG * cS, (long)cS,
        p_v, cD, (long)cS * cD, (long)cC,
        p_ao, cD, (long)cN * cD, (long)cC,
        nullptr, 0, 0,
        cN, cC, cS);

    // Projection + residual
    sgemm_nt<<<dim3(cD / 128, (cB * cN) / 128), 256>>>(p_ao, w_proj, p_p1, cB * cN, cD, cD, b_proj, parts);

    // Reason block
    ln_kernel<<<cB * cN, 256>>>(p_p1, nullptr, 0, reason_ln_w, reason_ln_b, p_t);
    gemm_nn<<<dim3(cD / 64, cN / 128, cB), 256>>>(
        reason_w, cN, 1, 0, 0,
        p_t, cD, (long)cN * cD, 0,
        p_p2, cD, (long)cN * cD, 0,
        p_p1, (long)cN * cD, 0,
        cN, cD, cN);

    // MLP
    ln_kernel<<<cB * cN, 256>>>(p_p2, nullptr, 0, mlp_ln_w, mlp_ln_b, p_t);
    sgemm_nt<<<dim3(cD / 128, (cB * cN) / 128), 256>>>(p_t, fc1_w, p_h, cB * cN, cD, cD, fc1_b, nullptr);
    gelu_kernel<<<(cB * cN * cD + 255) / 256, 256>>>(p_h, cB * cN * cD);
    sgemm_nt<<<dim3(cD / 128, (cB * cN) / 128), 256>>>(p_h, fc2_w, out_parts, cB * cN, cD, cD, fc2_b, p_p2);

    (void)in_sizes; (void)n_in; (void)out_size;
}

// round 2
// speedup vs baseline: 2.3794x; 2.3794x over previous
#include <cuda_runtime.h>
#include <math.h>
#include <stdint.h>

// Problem constants
constexpr int cB = 4;
constexpr int cS = 4096;
constexpr int cN = 256;
constexpr int cD = 1024;
constexpr int cG = 16;
constexpr int cC = 64;

// ---------------------------------------------------------------------------
// Scratch (static device arrays; no cudaMalloc anywhere)
// ---------------------------------------------------------------------------
__device__ float g_nbuf[cB * cS * cD];
__device__ float g_k[cB * cS * cD];
__device__ float g_v[cB * cS * cD];
__device__ float g_nq[cB * cN * cD];
__device__ float g_q[cB * cN * cD];
__device__ float g_ao[cB * cN * cD];
__device__ float g_p1[cB * cN * cD];
__device__ float g_p2[cB * cN * cD];
__device__ float g_t[cB * cN * cD];
__device__ float g_h[cB * cN * cD];
__device__ int   g_mask[cB * cS];
__device__ int   g_flag[1];

// ---------------------------------------------------------------------------
// tf32 helpers
// ---------------------------------------------------------------------------
__device__ __forceinline__ uint32_t f2tf(float f) {
    uint32_t u;
    asm("cvt.rna.tf32.f32 %0, %1;" : "=r"(u) : "f"(f));
    return u;
}

__device__ __forceinline__ void mma8(float* c, const uint32_t* a, const uint32_t* b) {
    asm volatile(
        "mma.sync.aligned.m16n8k8.row.col.f32.tf32.tf32.f32 "
        "{%0,%1,%2,%3}, {%4,%5,%6,%7}, {%8,%9}, {%0,%1,%2,%3};"
        : "+f"(c[0]), "+f"(c[1]), "+f"(c[2]), "+f"(c[3])
        : "r"(a[0]), "r"(a[1]), "r"(a[2]), "r"(a[3]), "r"(b[0]), "r"(b[1]));
}

// ---------------------------------------------------------------------------
// Mask dtype detection + expansion
// ---------------------------------------------------------------------------
__global__ void detect_mask_kernel(const unsigned char* __restrict__ p, int* flag) {
    __shared__ int red[256];
    int t = threadIdx.x;
    int cnt = 0;
    for (int i = t; i < cB * cS; i += 256)
        if ((i & 3) != 0 && p[i] != 0) cnt++;
    red[t] = cnt;
    __syncthreads();
    for (int s = 128; s > 0; s >>= 1) {
        if (t < s) red[t] += red[t + s];
        __syncthreads();
    }
    if (t == 0) flag[0] = red[0];
}

__global__ void expand_mask_kernel(const void* __restrict__ p, const int* __restrict__ flag,
                                   int* __restrict__ mout) {
    int i = blockIdx.x * 256 + threadIdx.x;
    if (i >= cB * cS) return;
    int isbyte = flag[0] > 0;
    int v = isbyte ? (int)((const unsigned char*)p)[i] : ((const int*)p)[i];
    mout[i] = (v != 0) ? 1 : 0;
}

// ---------------------------------------------------------------------------
// LayerNorm over D=1024. addmode: 0=none, 1=elementwise, 2=qpos broadcast
// ---------------------------------------------------------------------------
__global__ void ln_kernel(const float* __restrict__ x, const float* __restrict__ add,
                          int addmode, const float* __restrict__ w, const float* __restrict__ bias,
                          float* __restrict__ out) {
    __shared__ float row[cD];
    __shared__ float red[256];
    int r = blockIdx.x;
    int t = threadIdx.x;
    const float* xr = x + (size_t)r * cD;

    float lsum = 0.f;
    for (int i = t; i < cD; i += 256) {
        float v = xr[i];
        if (addmode == 1)      v += add[(size_t)r * cD + i];
        else if (addmode == 2) v += add[(size_t)r * cC + (i & (cC - 1))];
        row[i] = v;
        lsum += v;
    }
    red[t] = lsum;
    __syncthreads();
    for (int s = 128; s > 0; s >>= 1) {
        if (t < s) red[t] += red[t + s];
        __syncthreads();
    }
    float mu = red[0] * (1.f / cD);
    __syncthreads();

    float lvar = 0.f;
    for (int i = t; i < cD; i += 256) {
        float d = row[i] - mu;
        lvar += d * d;
    }
    red[t] = lvar;
    __syncthreads();
    for (int s = 128; s > 0; s >>= 1) {
        if (t < s) red[t] += red[t + s];
        __syncthreads();
    }
    float inv = rsqrtf(red[0] * (1.f / cD) + 1e-5f);
    for (int i = t; i < cD; i += 256)
        out[(size_t)r * cD + i] = (row[i] - mu) * inv * w[i] + bias[i];
}

// ---------------------------------------------------------------------------
// TF32 NT GEMM: C[M,Nc] = alpha * A[M,K] @ W[Nc,K]^T (+bias)(+resid)
// BN=128 fixed, BM template (128 or 64). 256 threads, 8 warps.
// Warp grid 2(m) x 4(n); warp tile (BM/2) x 32.
// smem layout [row][k] with stride 20 -> conflict-free fragment LDS.
// Batch via blockIdx.z with split offsets (zo = z/zdiv, zi = z%zdiv).
// ---------------------------------------------------------------------------
template <int BM>
__global__ void __launch_bounds__(256) tf32_nt(
    const float* __restrict__ A, long lda,
    const float* __restrict__ Bw, long ldb,
    float* __restrict__ Cp, long ldc,
    int K, float alpha,
    const float* __restrict__ bias, const float* __restrict__ resid,
    int zdiv, long a1, long a2, long b1, long b2, long c1, long c2) {
    constexpr int BN = 128;
    constexpr int LD = 20;
    constexpr int WTM = BM / 2;
    constexpr int MT = WTM / 16;   // m16 tiles per warp
    constexpr int AP = BM / 64;    // float4 loads per thread for A

    __shared__ float As[BM][LD];
    __shared__ float Bs[BN][LD];

    int t = threadIdx.x;
    int lane = t & 31;
    int warp = t >> 5;
    int z = blockIdx.z;
    int zo = z / zdiv, zi = z - zo * zdiv;

    const float* Ab = A + zo * a1 + zi * a2 + (long)blockIdx.y * BM * lda;
    const float* Bb = Bw + zo * b1 + zi * b2 + (long)blockIdx.x * BN * ldb;

    int wm0 = (warp & 1) * WTM;
    int wn0 = (warp >> 1) * 32;

    float acc[MT][4][4];
#pragma unroll
    for (int i = 0; i < MT; i++)
#pragma unroll
        for (int j = 0; j < 4; j++)
#pragma unroll
            for (int e = 0; e < 4; e++) acc[i][j][e] = 0.f;

    int lrow = t >> 2;
    int lcol = (t & 3) * 4;

    float4 pa[AP], pb[2];
    int nslab = K >> 4;

    // prologue: load slab 0
#pragma unroll
    for (int p = 0; p < AP; p++)
        pa[p] = *(const float4*)(Ab + (long)(lrow + p * 64) * lda + lcol);
#pragma unroll
    for (int p = 0; p < 2; p++)
        pb[p] = *(const float4*)(Bb + (long)(lrow + p * 64) * ldb + lcol);
#pragma unroll
    for (int p = 0; p < AP; p++)
        *(float4*)&As[lrow + p * 64][lcol] = pa[p];
#pragma unroll
    for (int p = 0; p < 2; p++)
        *(float4*)&Bs[lrow + p * 64][lcol] = pb[p];
    __syncthreads();

    int r0 = wm0 + (lane >> 2);
    int n0 = wn0 + (lane >> 2);
    int kc0 = lane & 3;

    for (int s = 0; s < nslab; s++) {
        if (s + 1 < nslab) {
            long k0 = (long)(s + 1) * 16;
#pragma unroll
            for (int p = 0; p < AP; p++)
                pa[p] = *(const float4*)(Ab + (long)(lrow + p * 64) * lda + k0 + lcol);
#pragma unroll
            for (int p = 0; p < 2; p++)
                pb[p] = *(const float4*)(Bb + (long)(lrow + p * 64) * ldb + k0 + lcol);
        }
#pragma unroll
        for (int kq = 0; kq < 2; kq++) {
            int kc = kq * 8 + kc0;
            uint32_t af[MT][4], bf[4][2];
#pragma unroll
            for (int i = 0; i < MT; i++) {
                af[i][0] = f2tf(As[r0 + i * 16][kc]);
                af[i][1] = f2tf(As[r0 + i * 16 + 8][kc]);
                af[i][2] = f2tf(As[r0 + i * 16][kc + 4]);
                af[i][3] = f2tf(As[r0 + i * 16 + 8][kc + 4]);
            }
#pragma unroll
            for (int j = 0; j < 4; j++) {
                bf[j][0] = f2tf(Bs[n0 + j * 8][kc]);
                bf[j][1] = f2tf(Bs[n0 + j * 8][kc + 4]);
            }
#pragma unroll
            for (int i = 0; i < MT; i++)
#pragma unroll
                for (int j = 0; j < 4; j++) mma8(acc[i][j], af[i], bf[j]);
        }
        __syncthreads();
        if (s + 1 < nslab) {
#pragma unroll
            for (int p = 0; p < AP; p++)
                *(float4*)&As[lrow + p * 64][lcol] = pa[p];
#pragma unroll
            for (int p = 0; p < 2; p++)
                *(float4*)&Bs[lrow + p * 64][lcol] = pb[p];
            __syncthreads();
        }
    }

    float* Cb = Cp + zo * c1 + zi * c2;
    const float* Rb = resid ? (resid + zo * c1 + zi * c2) : (const float*)nullptr;
    long ccol0 = (long)blockIdx.x * BN + wn0;
#pragma unroll
    for (int i = 0; i < MT; i++) {
#pragma unroll
        for (int half = 0; half < 2; half++) {
            long row = (long)blockIdx.y * BM + wm0 + i * 16 + (lane >> 2) + half * 8;
#pragma unroll
            for (int j = 0; j < 4; j++) {
                long col = ccol0 + j * 8 + 2 * (lane & 3);
                float2 o;
                o.x = acc[i][j][half * 2 + 0] * alpha;
                o.y = acc[i][j][half * 2 + 1] * alpha;
                if (bias) {
                    o.x += bias[col];
                    o.y += bias[col + 1];
                }
                long off = row * ldc + col;
                if (Rb) {
                    float2 rv = *(const float2*)&Rb[off];
                    o.x += rv.x; o.y += rv.y;
                }
                *(float2*)&Cb[off] = o;
            }
        }
    }
}

// ---------------------------------------------------------------------------
// TF32 NN GEMM: C[M,Nc] = A[M,K] @ B[K,Nc] (+resid)
// BM=128, BN=64, BK=16, 256 threads. Warp grid 4(m) x 2(n); warp tile 32x32.
// A smem [row][k] stride 20 (conflict-free); B smem [k][n] stride 72
// (conflict-free loads, conflict-free stores).
// ---------------------------------------------------------------------------
__global__ void __launch_bounds__(256) tf32_nn(
    const float* __restrict__ A, long lda,
    const float* __restrict__ Bm, long ldb,
    float* __restrict__ Cp, long ldc,
    int K,
    const float* __restrict__ resid,
    int zdiv, long a1, long a2, long b1, long b2, long c1, long c2) {
    constexpr int BM = 128;
    constexpr int BN = 64;
    constexpr int LDA_S = 20;
    constexpr int LDB_S = 72;

    __shared__ float As[BM][LDA_S];
    __shared__ float Bs[16][LDB_S];

    int t = threadIdx.x;
    int lane = t & 31;
    int warp = t >> 5;
    int z = blockIdx.z;
    int zo = z / zdiv, zi = z - zo * zdiv;

    const float* Ab = A + zo * a1 + zi * a2 + (long)blockIdx.y * BM * lda;
    const float* Bb = Bm + zo * b1 + zi * b2 + (long)blockIdx.x * BN;

    int wm0 = (warp & 3) * 32;
    int wn0 = (warp >> 2) * 32;

    float acc[2][4][4];
#pragma unroll
    for (int i = 0; i < 2; i++)
#pragma unroll
        for (int j = 0; j < 4; j++)
#pragma unroll
            for (int e = 0; e < 4; e++) acc[i][j][e] = 0.f;

    int arow = t >> 2;
    int acol = (t & 3) * 4;
    int brow = t >> 4;          // 0..15 (k)
    int bcol = (t & 15) * 4;    // 0..60 (n)

    float4 pa[2], pb;
    int nslab = K >> 4;

#pragma unroll
    for (int p = 0; p < 2; p++)
        pa[p] = *(const float4*)(Ab + (long)(arow + p * 64) * lda + acol);
    pb = *(const float4*)(Bb + (long)brow * ldb + bcol);
#pragma unroll
    for (int p = 0; p < 2; p++)
        *(float4*)&As[arow + p * 64][acol] = pa[p];
    *(float4*)&Bs[brow][bcol] = pb;
    __syncthreads();

    int r0 = wm0 + (lane >> 2);
    int n0 = wn0 + (lane >> 2);
    int kc0 = lane & 3;

    for (int s = 0; s < nslab; s++) {
        if (s + 1 < nslab) {
            long k0 = (long)(s + 1) * 16;
#pragma unroll
            for (int p = 0; p < 2; p++)
                pa[p] = *(const float4*)(Ab + (long)(arow + p * 64) * lda + k0 + acol);
            pb = *(const float4*)(Bb + (k0 + brow) * ldb + bcol);
        }
#pragma unroll
        for (int kq = 0; kq < 2; kq++) {
            int kc = kq * 8 + kc0;
            uint32_t af[2][4], bf[4][2];
#pragma unroll
            for (int i = 0; i < 2; i++) {
                af[i][0] = f2tf(As[r0 + i * 16][kc]);
                af[i][1] = f2tf(As[r0 + i * 16 + 8][kc]);
                af[i][2] = f2tf(As[r0 + i * 16][kc + 4]);
                af[i][3] = f2tf(As[r0 + i * 16 + 8][kc + 4]);
            }
#pragma unroll
            for (int j = 0; j < 4; j++) {
                bf[j][0] = f2tf(Bs[kc][n0 + j * 8]);
                bf[j][1] = f2tf(Bs[kc + 4][n0 + j * 8]);
            }
#pragma unroll
            for (int i = 0; i < 2; i++)
#pragma unroll
                for (int j = 0; j < 4; j++) mma8(acc[i][j], af[i], bf[j]);
        }
        __syncthreads();
        if (s + 1 < nslab) {
#pragma unroll
            for (int p = 0; p < 2; p++)
                *(float4*)&As[arow + p * 64][acol] = pa[p];
            *(float4*)&Bs[brow][bcol] = pb;
            __syncthreads();
        }
    }

    float* Cb = Cp + zo * c1 + zi * c2;
    const float* Rb = resid ? (resid + zo * c1 + zi * c2) : (const float*)nullptr;
    long ccol0 = (long)blockIdx.x * BN + wn0;
#pragma unroll
    for (int i = 0; i < 2; i++) {
#pragma unroll
        for (int half = 0; half < 2; half++) {
            long row = (long)blockIdx.y * BM + wm0 + i * 16 + (lane >> 2) + half * 8;
#pragma unroll
            for (int j = 0; j < 4; j++) {
                long col = ccol0 + j * 8 + 2 * (lane & 3);
                float2 o;
                o.x = acc[i][j][half * 2 + 0];
                o.y = acc[i][j][half * 2 + 1];
                long off = row * ldc + col;
                if (Rb) {
                    float2 rv = *(const float2*)&Rb[off];
                    o.x += rv.x; o.y += rv.y;
                }
                *(float2*)&Cb[off] = o;
            }
        }
    }
}

// ---------------------------------------------------------------------------
// Masked softmax over S, one block per (b,n,g) row, in place.
// ---------------------------------------------------------------------------
__global__ void softmax_kernel(float* __restrict__ attn, const int* __restrict__ mask) {
    __shared__ float red[256];
    int r = blockIdx.x;
    int t = threadIdx.x;
    int b = r / (cN * cG);
    float* rowp = attn + (size_t)r * cS;
    const int* mrow = mask + b * cS;

    float vals[16];
    int msk[16];
    float mx = -INFINITY;
#pragma unroll
    for (int i = 0; i < 16; i++) {
        int s = t + i * 256;
        msk[i] = mrow[s];
        vals[i] = rowp[s];
        if (!msk[i]) mx = fmaxf(mx, vals[i]);
    }
    red[t] = mx;
    __syncthreads();
    for (int s = 128; s > 0; s >>= 1) {
        if (t < s) red[t] = fmaxf(red[t], red[t + s]);
        __syncthreads();
    }
    mx = red[0];
    __syncthreads();

    float sum = 0.f;
#pragma unroll
    for (int i = 0; i < 16; i++) {
        float e = msk[i] ? 0.f : expf(vals[i] - mx);
        vals[i] = e;
        sum += e;
    }
    red[t] = sum;
    __syncthreads();
    for (int s = 128; s > 0; s >>= 1) {
        if (t < s) red[t] += red[t + s];
        __syncthreads();
    }
    float inv = (red[0] > 0.f) ? 1.f / red[0] : 0.f;
#pragma unroll
    for (int i = 0; i < 16; i++)
        rowp[t + i * 256] = vals[i] * inv;
}

// ---------------------------------------------------------------------------
// Exact GELU
// ---------------------------------------------------------------------------
__global__ void gelu_kernel(float* __restrict__ x, int n) {
    int i = blockIdx.x * 256 + threadIdx.x;
    if (i >= n) return;
    float v = x[i];
    x[i] = 0.5f * v * (1.f + erff(v * 0.70710678118654752f));
}

// ---------------------------------------------------------------------------
// Host launcher
// ---------------------------------------------------------------------------
extern "C" void kernel_launch(void* const* d_in, const int* in_sizes, int n_in,
                              void* d_out, int out_size) {
    const float* feats   = (const float*)d_in[0];
    const float* parts   = (const float*)d_in[1];
    const float* qpos    = (const float*)d_in[2];
    const float* kpos    = (const float*)d_in[3];
    const void*  maskraw = d_in[4];
    const float* ln_q_w  = (const float*)d_in[5];
    const float* ln_q_b  = (const float*)d_in[6];
    const float* ln_k_w  = (const float*)d_in[7];
    const float* ln_k_b  = (const float*)d_in[8];
    const float* ln_v_w  = (const float*)d_in[9];
    const float* ln_v_b  = (const float*)d_in[10];
    const float* wq      = (const float*)d_in[11];
    const float* wk      = (const float*)d_in[12];
    const float* wv      = (const float*)d_in[13];
    const float* w_proj  = (const float*)d_in[14];
    const float* b_proj  = (const float*)d_in[15];
    const float* reason_ln_w = (const float*)d_in[16];
    const float* reason_ln_b = (const float*)d_in[17];
    const float* reason_w    = (const float*)d_in[18];
    const float* mlp_ln_w    = (const float*)d_in[19];
    const float* mlp_ln_b    = (const float*)d_in[20];
    const float* fc1_w   = (const float*)d_in[21];
    const float* fc1_b   = (const float*)d_in[22];
    const float* fc2_w   = (const float*)d_in[23];
    const float* fc2_b   = (const float*)d_in[24];

    float* out_parts = (float*)d_out;
    float* out_attn  = out_parts + (size_t)cB * cN * cD;

    float *p_nbuf, *p_k, *p_v, *p_nq, *p_q, *p_ao, *p_p1, *p_p2, *p_t, *p_h;
    int *p_mask, *p_flag;
    cudaGetSymbolAddress((void**)&p_nbuf, g_nbuf);
    cudaGetSymbolAddress((void**)&p_k, g_k);
    cudaGetSymbolAddress((void**)&p_v, g_v);
    cudaGetSymbolAddress((void**)&p_nq, g_nq);
    cudaGetSymbolAddress((void**)&p_q, g_q);
    cudaGetSymbolAddress((void**)&p_ao, g_ao);
    cudaGetSymbolAddress((void**)&p_p1, g_p1);
    cudaGetSymbolAddress((void**)&p_p2, g_p2);
    cudaGetSymbolAddress((void**)&p_t, g_t);
    cudaGetSymbolAddress((void**)&p_h, g_h);
    cudaGetSymbolAddress((void**)&p_mask, g_mask);
    cudaGetSymbolAddress((void**)&p_flag, g_flag);

    detect_mask_kernel<<<1, 256>>>((const unsigned char*)maskraw, p_flag);
    expand_mask_kernel<<<(cB * cS + 255) / 256, 256>>>(maskraw, p_flag, p_mask);

    // Q path: LN(+qpos) -> Wq^T  (M = B*N = 1024)
    ln_kernel<<<cB * cN, 256>>>(parts, qpos, 2, ln_q_w, ln_q_b, p_nq);
    tf32_nt<64><<<dim3(cD / 128, (cB * cN) / 64, 1), 256>>>(
        p_nq, cD, wq, cD, p_q, cD, cD, 1.f, nullptr, nullptr, 1, 0, 0, 0, 0, 0, 0);

    // K path (M = B*S = 16384)
    ln_kernel<<<cB * cS, 256>>>(feats, kpos, 1, ln_k_w, ln_k_b, p_nbuf);
    tf32_nt<128><<<dim3(cD / 128, (cB * cS) / 128, 1), 256>>>(
        p_nbuf, cD, wk, cD, p_k, cD, cD, 1.f, nullptr, nullptr, 1, 0, 0, 0, 0, 0, 0);

    // V path
    ln_kernel<<<cB * cS, 256>>>(feats, nullptr, 0, ln_v_w, ln_v_b, p_nbuf);
    tf32_nt<128><<<dim3(cD / 128, (cB * cS) / 128, 1), 256>>>(
        p_nbuf, cD, wv, cD, p_v, cD, cD, 1.f, nullptr, nullptr, 1, 0, 0, 0, 0, 0, 0);

    // Scores: attn[b,n,g,s] = 0.125 * q . k   (batched over z = b*G + g)
    tf32_nt<128><<<dim3(cS / 128, cN / 128, cB * cG), 256>>>(
        p_q, cD, p_k, cD, out_attn, (long)cG * cS, cC, 0.125f, nullptr, nullptr,
        cG,
        (long)cN * cD, (long)cC,            // a: per-b, per-g
        (long)cS * cD, (long)cC,            // b: per-b, per-g
        (long)cN * cG * cS, (long)cS);      // c: per-b, per-g

    softmax_kernel<<<cB * cN * cG, 256>>>(out_attn, p_mask);

    // AV: ao[b,n,g,c] = attn[b,n,g,:] @ v[b,:,g,c]   (NN, K = S)
    tf32_nn<<<dim3(cC / 64, cN / 128, cB * cG), 256>>>(
        out_attn, (long)cG * cS, p_v, cD, p_ao, cD, cS, nullptr,
        cG,
        (long)cN * cG * cS, (long)cS,
        (long)cS * cD, (long)cC,
        (long)cN * cD, (long)cC);

    // Projection + residual (M = 1024)
    tf32_nt<64><<<dim3(cD / 128, (cB * cN) / 64, 1), 256>>>(
        p_ao, cD, w_proj, cD, p_p1, cD, cD, 1.f, b_proj, parts, 1, 0, 0, 0, 0, 0, 0);

    // Reason block: p2 = p1 + reason_w @ LN(p1)
    ln_kernel<<<cB * cN, 256>>>(p_p1, nullptr, 0, reason_ln_w, reason_ln_b, p_t);
    tf32_nn<<<dim3(cD / 64, cN / 128, cB), 256>>>(
        reason_w, cN, p_t, cD, p_p2, cD, cN, p_p1,
        1,
        0, 0,
        (long)cN * cD, 0,
        (long)cN * cD, 0);

    // MLP
    ln_kernel<<<cB * cN, 256>>>(p_p2, nullptr, 0, mlp_ln_w, mlp_ln_b, p_t);
    tf32_nt<64><<<dim3(cD / 128, (cB * cN) / 64, 1), 256>>>(
        p_t, cD, fc1_w, cD, p_h, cD, cD, 1.f, fc1_b, nullptr, 1, 0, 0, 0, 0, 0, 0);
    gelu_kernel<<<(cB * cN * cD + 255) / 256, 256>>>(p_h, cB * cN * cD);
    tf32_nt<64><<<dim3(cD / 128, (cB * cN) / 64, 1), 256>>>(
        p_h, cD, fc2_w, cD, out_parts, cD, cD, 1.f, fc2_b, p_p2, 1, 0, 0, 0, 0, 0, 0);

    (void)in_sizes; (void)n_in; (void)out_size;
}

// round 3
// speedup vs baseline: 2.5120x; 1.0557x over previous
#include <cuda_runtime.h>
#include <math.h>
#include <stdint.h>

// Problem constants
constexpr int cB = 4;
constexpr int cS = 4096;
constexpr int cN = 256;
constexpr int cD = 1024;
constexpr int cG = 16;
constexpr int cC = 64;

// ---------------------------------------------------------------------------
// Scratch (static device arrays; no cudaMalloc anywhere)
// ---------------------------------------------------------------------------
__device__ float g_nbuf[cB * cS * cD];
__device__ float g_k[cB * cS * cD];
__device__ float g_v[cB * cS * cD];
__device__ float g_nq[cB * cN * cD];
__device__ float g_q[cB * cN * cD];
__device__ float g_ao[cB * cN * cD];
__device__ float g_p1[cB * cN * cD];
__device__ float g_p2[cB * cN * cD];
__device__ float g_t[cB * cN * cD];
__device__ float g_h[cB * cN * cD];
__device__ int   g_mask[cB * cS];
__device__ int   g_flag[1];

// ---------------------------------------------------------------------------
// tf32 helpers
// ---------------------------------------------------------------------------
__device__ __forceinline__ uint32_t f2tf(float f) {
    uint32_t u;
    asm("cvt.rna.tf32.f32 %0, %1;" : "=r"(u) : "f"(f));
    return u;
}

__device__ __forceinline__ void mma8(float* c, const uint32_t* a, const uint32_t* b) {
    asm volatile(
        "mma.sync.aligned.m16n8k8.row.col.f32.tf32.tf32.f32 "
        "{%0,%1,%2,%3}, {%4,%5,%6,%7}, {%8,%9}, {%0,%1,%2,%3};"
        : "+f"(c[0]), "+f"(c[1]), "+f"(c[2]), "+f"(c[3])
        : "r"(a[0]), "r"(a[1]), "r"(a[2]), "r"(a[3]), "r"(b[0]), "r"(b[1]));
}

__device__ __forceinline__ void cvt4(uint32_t* d, float4 v) {
    d[0] = f2tf(v.x); d[1] = f2tf(v.y); d[2] = f2tf(v.z); d[3] = f2tf(v.w);
}

// ---------------------------------------------------------------------------
// Mask dtype detection + expansion
// ---------------------------------------------------------------------------
__global__ void detect_mask_kernel(const unsigned char* __restrict__ p, int* flag) {
    __shared__ int red[256];
    int t = threadIdx.x;
    int cnt = 0;
    for (int i = t; i < cB * cS; i += 256)
        if ((i & 3) != 0 && p[i] != 0) cnt++;
    red[t] = cnt;
    __syncthreads();
    for (int s = 128; s > 0; s >>= 1) {
        if (t < s) red[t] += red[t + s];
        __syncthreads();
    }
    if (t == 0) flag[0] = red[0];
}

__global__ void expand_mask_kernel(const void* __restrict__ p, const int* __restrict__ flag,
                                   int* __restrict__ mout) {
    int i = blockIdx.x * 256 + threadIdx.x;
    if (i >= cB * cS) return;
    int isbyte = flag[0] > 0;
    int v = isbyte ? (int)((const unsigned char*)p)[i] : ((const int*)p)[i];
    mout[i] = (v != 0) ? 1 : 0;
}

// ---------------------------------------------------------------------------
// LayerNorm over D=1024. addmode: 0=none, 1=elementwise, 2=qpos broadcast
// ---------------------------------------------------------------------------
__global__ void ln_kernel(const float* __restrict__ x, const float* __restrict__ add,
                          int addmode, const float* __restrict__ w, const float* __restrict__ bias,
                          float* __restrict__ out) {
    __shared__ float row[cD];
    __shared__ float red[256];
    int r = blockIdx.x;
    int t = threadIdx.x;
    const float* xr = x + (size_t)r * cD;

    float lsum = 0.f;
    for (int i = t; i < cD; i += 256) {
        float v = xr[i];
        if (addmode == 1)      v += add[(size_t)r * cD + i];
        else if (addmode == 2) v += add[(size_t)r * cC + (i & (cC - 1))];
        row[i] = v;
        lsum += v;
    }
    red[t] = lsum;
    __syncthreads();
    for (int s = 128; s > 0; s >>= 1) {
        if (t < s) red[t] += red[t + s];
        __syncthreads();
    }
    float mu = red[0] * (1.f / cD);
    __syncthreads();

    float lvar = 0.f;
    for (int i = t; i < cD; i += 256) {
        float d = row[i] - mu;
        lvar += d * d;
    }
    red[t] = lvar;
    __syncthreads();
    for (int s = 128; s > 0; s >>= 1) {
        if (t < s) red[t] += red[t + s];
        __syncthreads();
    }
    float inv = rsqrtf(red[0] * (1.f / cD) + 1e-5f);
    for (int i = t; i < cD; i += 256)
        out[(size_t)r * cD + i] = (row[i] - mu) * inv * w[i] + bias[i];
}

// ---------------------------------------------------------------------------
// TF32 NT GEMM: C[M,Nc] = alpha * A[M,K] @ W[Nc,K]^T (+bias)(+resid)
// smem holds pre-converted tf32 bits; 256 threads, 8 warps, BK=16, dbl-buffered
// registers. Warp grid: BN=128 -> 2m x 4n; BN=64 -> 4m x 2n.
// ---------------------------------------------------------------------------
template <int BM, int BN>
__global__ void __launch_bounds__(256) tf32_nt(
    const float* __restrict__ A, long lda,
    const float* __restrict__ Bw, long ldb,
    float* __restrict__ Cp, long ldc,
    int K, float alpha,
    const float* __restrict__ bias, const float* __restrict__ resid,
    int zdiv, long a1, long a2, long b1, long b2, long c1, long c2) {
    constexpr int LD = 20;
    constexpr int WN = (BN == 128) ? 4 : 2;
    constexpr int WM = 8 / WN;
    constexpr int MT = BM / (16 * WM);
    constexpr int NT = BN / (8 * WN);
    constexpr int AP = BM / 64;
    constexpr int BP = BN / 64;

    __shared__ uint32_t As[BM][LD];
    __shared__ uint32_t Bs[BN][LD];

    int t = threadIdx.x;
    int lane = t & 31;
    int warp = t >> 5;
    int z = blockIdx.z;
    int zo = z / zdiv, zi = z - zo * zdiv;

    const float* Ab = A + zo * a1 + zi * a2 + (long)blockIdx.y * BM * lda;
    const float* Bb = Bw + zo * b1 + zi * b2 + (long)blockIdx.x * BN * ldb;

    int wm0 = (warp % WM) * (BM / WM);
    int wn0 = (warp / WM) * (BN / WN);

    float acc[MT][NT][4];
#pragma unroll
    for (int i = 0; i < MT; i++)
#pragma unroll
        for (int j = 0; j < NT; j++)
#pragma unroll
            for (int e = 0; e < 4; e++) acc[i][j][e] = 0.f;

    int lrow = t >> 2;
    int lcol = (t & 3) * 4;

    uint32_t pa[AP][4], pb[BP][4];
    int nslab = K >> 4;

#pragma unroll
    for (int p = 0; p < AP; p++)
        cvt4(pa[p], *(const float4*)(Ab + (long)(lrow + p * 64) * lda + lcol));
#pragma unroll
    for (int p = 0; p < BP; p++)
        cvt4(pb[p], *(const float4*)(Bb + (long)(lrow + p * 64) * ldb + lcol));
#pragma unroll
    for (int p = 0; p < AP; p++)
        *(uint4*)&As[lrow + p * 64][lcol] = *(uint4*)pa[p];
#pragma unroll
    for (int p = 0; p < BP; p++)
        *(uint4*)&Bs[lrow + p * 64][lcol] = *(uint4*)pb[p];
    __syncthreads();

    int r0 = wm0 + (lane >> 2);
    int n0 = wn0 + (lane >> 2);
    int kc0 = lane & 3;

    for (int s = 0; s < nslab; s++) {
        if (s + 1 < nslab) {
            long k0 = (long)(s + 1) * 16;
#pragma unroll
            for (int p = 0; p < AP; p++)
                cvt4(pa[p], *(const float4*)(Ab + (long)(lrow + p * 64) * lda + k0 + lcol));
#pragma unroll
            for (int p = 0; p < BP; p++)
                cvt4(pb[p], *(const float4*)(Bb + (long)(lrow + p * 64) * ldb + k0 + lcol));
        }
#pragma unroll
        for (int kq = 0; kq < 2; kq++) {
            int kc = kq * 8 + kc0;
            uint32_t af[MT][4], bf[NT][2];
#pragma unroll
            for (int i = 0; i < MT; i++) {
                af[i][0] = As[r0 + i * 16][kc];
                af[i][1] = As[r0 + i * 16 + 8][kc];
                af[i][2] = As[r0 + i * 16][kc + 4];
                af[i][3] = As[r0 + i * 16 + 8][kc + 4];
            }
#pragma unroll
            for (int j = 0; j < NT; j++) {
                bf[j][0] = Bs[n0 + j * 8][kc];
                bf[j][1] = Bs[n0 + j * 8][kc + 4];
            }
#pragma unroll
            for (int i = 0; i < MT; i++)
#pragma unroll
                for (int j = 0; j < NT; j++) mma8(acc[i][j], af[i], bf[j]);
        }
        __syncthreads();
        if (s + 1 < nslab) {
#pragma unroll
            for (int p = 0; p < AP; p++)
                *(uint4*)&As[lrow + p * 64][lcol] = *(uint4*)pa[p];
#pragma unroll
            for (int p = 0; p < BP; p++)
                *(uint4*)&Bs[lrow + p * 64][lcol] = *(uint4*)pb[p];
            __syncthreads();
        }
    }

    float* Cb = Cp + zo * c1 + zi * c2;
    const float* Rb = resid ? (resid + zo * c1 + zi * c2) : (const float*)nullptr;
    long ccol0 = (long)blockIdx.x * BN + wn0;
#pragma unroll
    for (int i = 0; i < MT; i++) {
#pragma unroll
        for (int half = 0; half < 2; half++) {
            long row = (long)blockIdx.y * BM + wm0 + i * 16 + (lane >> 2) + half * 8;
#pragma unroll
            for (int j = 0; j < NT; j++) {
                long col = ccol0 + j * 8 + 2 * (lane & 3);
                float2 o;
                o.x = acc[i][j][half * 2 + 0] * alpha;
                o.y = acc[i][j][half * 2 + 1] * alpha;
                if (bias) {
                    o.x += bias[col];
                    o.y += bias[col + 1];
                }
                long off = row * ldc + col;
                if (Rb) {
                    float2 rv = *(const float2*)&Rb[off];
                    o.x += rv.x; o.y += rv.y;
                }
                *(float2*)&Cb[off] = o;
            }
        }
    }
}

// ---------------------------------------------------------------------------
// TF32 NN GEMM: C[M,Nc] = A[M,K] @ B[K,Nc] (+resid)
// BM=64, BN=64, BK=16, 256 threads. Warp grid 4m x 2n; warp tile 16x32.
// A smem [row][k] stride 20; B smem [k][n] stride 72. tf32 bits in smem.
// ---------------------------------------------------------------------------
__global__ void __launch_bounds__(256) tf32_nn(
    const float* __restrict__ A, long lda,
    const float* __restrict__ Bm, long ldb,
    float* __restrict__ Cp, long ldc,
    int K,
    const float* __restrict__ resid,
    int zdiv, long a1, long a2, long b1, long b2, long c1, long c2) {
    constexpr int BM = 64;
    constexpr int BN = 64;
    constexpr int LDA_S = 20;
    constexpr int LDB_S = 72;

    __shared__ uint32_t As[BM][LDA_S];
    __shared__ uint32_t Bs[16][LDB_S];

    int t = threadIdx.x;
    int lane = t & 31;
    int warp = t >> 5;
    int z = blockIdx.z;
    int zo = z / zdiv, zi = z - zo * zdiv;

    const float* Ab = A + zo * a1 + zi * a2 + (long)blockIdx.y * BM * lda;
    const float* Bb = Bm + zo * b1 + zi * b2 + (long)blockIdx.x * BN;

    int wm0 = (warp & 3) * 16;          // 4 m-warps, warp tile 16 rows
    int wn0 = (warp >> 2) * 32;         // 2 n-warps, warp tile 32 cols

    float acc[4][4];                    // MT=1, NT=4
#pragma unroll
    for (int j = 0; j < 4; j++)
#pragma unroll
        for (int e = 0; e < 4; e++) acc[j][e] = 0.f;

    int arow = t >> 2;
    int acol = (t & 3) * 4;
    int brow = t >> 4;
    int bcol = (t & 15) * 4;

    uint32_t pa[4], pb[4];
    int nslab = K >> 4;

    cvt4(pa, *(const float4*)(Ab + (long)arow * lda + acol));
    cvt4(pb, *(const float4*)(Bb + (long)brow * ldb + bcol));
    *(uint4*)&As[arow][acol] = *(uint4*)pa;
    *(uint4*)&Bs[brow][bcol] = *(uint4*)pb;
    __syncthreads();

    int r0 = wm0 + (lane >> 2);
    int n0 = wn0 + (lane >> 2);
    int kc0 = lane & 3;

    for (int s = 0; s < nslab; s++) {
        if (s + 1 < nslab) {
            long k0 = (long)(s + 1) * 16;
            cvt4(pa, *(const float4*)(Ab + (long)arow * lda + k0 + acol));
            cvt4(pb, *(const float4*)(Bb + (k0 + brow) * ldb + bcol));
        }
#pragma unroll
        for (int kq = 0; kq < 2; kq++) {
            int kc = kq * 8 + kc0;
            uint32_t af[4], bf[4][2];
            af[0] = As[r0][kc];
            af[1] = As[r0 + 8][kc];
            af[2] = As[r0][kc + 4];
            af[3] = As[r0 + 8][kc + 4];
#pragma unroll
            for (int j = 0; j < 4; j++) {
                bf[j][0] = Bs[kc][n0 + j * 8];
                bf[j][1] = Bs[kc + 4][n0 + j * 8];
            }
#pragma unroll
            for (int j = 0; j < 4; j++) mma8(acc[j], af, bf[j]);
        }
        __syncthreads();
        if (s + 1 < nslab) {
            *(uint4*)&As[arow][acol] = *(uint4*)pa;
            *(uint4*)&Bs[brow][bcol] = *(uint4*)pb;
            __syncthreads();
        }
    }

    float* Cb = Cp + zo * c1 + zi * c2;
    const float* Rb = resid ? (resid + zo * c1 + zi * c2) : (const float*)nullptr;
    long ccol0 = (long)blockIdx.x * BN + wn0;
#pragma unroll
    for (int half = 0; half < 2; half++) {
        long row = (long)blockIdx.y * BM + wm0 + (lane >> 2) + half * 8;
#pragma unroll
        for (int j = 0; j < 4; j++) {
            long col = ccol0 + j * 8 + 2 * (lane & 3);
            float2 o;
            o.x = acc[j][half * 2 + 0];
            o.y = acc[j][half * 2 + 1];
            long off = row * ldc + col;
            if (Rb) {
                float2 rv = *(const float2*)&Rb[off];
                o.x += rv.x; o.y += rv.y;
            }
            *(float2*)&Cb[off] = o;
        }
    }
}

// ---------------------------------------------------------------------------
// Masked softmax over S, one block per (b,n,g) row, in place.
// ---------------------------------------------------------------------------
__global__ void softmax_kernel(float* __restrict__ attn, const int* __restrict__ mask) {
    __shared__ float red[256];
    int r = blockIdx.x;
    int t = threadIdx.x;
    int b = r / (cN * cG);
    float* rowp = attn + (size_t)r * cS;
    const int* mrow = mask + b * cS;

    float vals[16];
    int msk[16];
    float mx = -INFINITY;
#pragma unroll
    for (int i = 0; i < 16; i++) {
        int s = t + i * 256;
        msk[i] = mrow[s];
        vals[i] = rowp[s];
        if (!msk[i]) mx = fmaxf(mx, vals[i]);
    }
    red[t] = mx;
    __syncthreads();
    for (int s = 128; s > 0; s >>= 1) {
        if (t < s) red[t] = fmaxf(red[t], red[t + s]);
        __syncthreads();
    }
    mx = red[0];
    __syncthreads();

    float sum = 0.f;
#pragma unroll
    for (int i = 0; i < 16; i++) {
        float e = msk[i] ? 0.f : __expf(vals[i] - mx);
        vals[i] = e;
        sum += e;
    }
    red[t] = sum;
    __syncthreads();
    for (int s = 128; s > 0; s >>= 1) {
        if (t < s) red[t] += red[t + s];
        __syncthreads();
    }
    float inv = (red[0] > 0.f) ? 1.f / red[0] : 0.f;
#pragma unroll
    for (int i = 0; i < 16; i++)
        rowp[t + i * 256] = vals[i] * inv;
}

// ---------------------------------------------------------------------------
// Exact GELU
// ---------------------------------------------------------------------------
__global__ void gelu_kernel(float* __restrict__ x, int n) {
    int i = blockIdx.x * 256 + threadIdx.x;
    if (i >= n) return;
    float v = x[i];
    x[i] = 0.5f * v * (1.f + erff(v * 0.70710678118654752f));
}

// ---------------------------------------------------------------------------
// Host launcher
// ---------------------------------------------------------------------------
extern "C" void kernel_launch(void* const* d_in, const int* in_sizes, int n_in,
                              void* d_out, int out_size) {
    const float* feats   = (const float*)d_in[0];
    const float* parts   = (const float*)d_in[1];
    const float* qpos    = (const float*)d_in[2];
    const float* kpos    = (const float*)d_in[3];
    const void*  maskraw = d_in[4];
    const float* ln_q_w  = (const float*)d_in[5];
    const float* ln_q_b  = (const float*)d_in[6];
    const float* ln_k_w  = (const float*)d_in[7];
    const float* ln_k_b  = (const float*)d_in[8];
    const float* ln_v_w  = (const float*)d_in[9];
    const float* ln_v_b  = (const float*)d_in[10];
    const float* wq      = (const float*)d_in[11];
    const float* wk      = (const float*)d_in[12];
    const float* wv      = (const float*)d_in[13];
    const float* w_proj  = (const float*)d_in[14];
    const float* b_proj  = (const float*)d_in[15];
    const float* reason_ln_w = (const float*)d_in[16];
    const float* reason_ln_b = (const float*)d_in[17];
    const float* reason_w    = (const float*)d_in[18];
    const float* mlp_ln_w    = (const float*)d_in[19];
    const float* mlp_ln_b    = (const float*)d_in[20];
    const float* fc1_w   = (const float*)d_in[21];
    const float* fc1_b   = (const float*)d_in[22];
    const float* fc2_w   = (const float*)d_in[23];
    const float* fc2_b   = (const float*)d_in[24];

    float* out_parts = (float*)d_out;
    float* out_attn  = out_parts + (size_t)cB * cN * cD;

    float *p_nbuf, *p_k, *p_v, *p_nq, *p_q, *p_ao, *p_p1, *p_p2, *p_t, *p_h;
    int *p_mask, *p_flag;
    cudaGetSymbolAddress((void**)&p_nbuf, g_nbuf);
    cudaGetSymbolAddress((void**)&p_k, g_k);
    cudaGetSymbolAddress((void**)&p_v, g_v);
    cudaGetSymbolAddress((void**)&p_nq, g_nq);
    cudaGetSymbolAddress((void**)&p_q, g_q);
    cudaGetSymbolAddress((void**)&p_ao, g_ao);
    cudaGetSymbolAddress((void**)&p_p1, g_p1);
    cudaGetSymbolAddress((void**)&p_p2, g_p2);
    cudaGetSymbolAddress((void**)&p_t, g_t);
    cudaGetSymbolAddress((void**)&p_h, g_h);
    cudaGetSymbolAddress((void**)&p_mask, g_mask);
    cudaGetSymbolAddress((void**)&p_flag, g_flag);

    detect_mask_kernel<<<1, 256>>>((const unsigned char*)maskraw, p_flag);
    expand_mask_kernel<<<(cB * cS + 255) / 256, 256>>>(maskraw, p_flag, p_mask);

    // Q path: LN(+qpos) -> Wq^T  (M = 1024)
    ln_kernel<<<cB * cN, 256>>>(parts, qpos, 2, ln_q_w, ln_q_b, p_nq);
    tf32_nt<64, 64><<<dim3(cD / 64, (cB * cN) / 64, 1), 256>>>(
        p_nq, cD, wq, cD, p_q, cD, cD, 1.f, nullptr, nullptr, 1, 0, 0, 0, 0, 0, 0);

    // K path (M = 16384)
    ln_kernel<<<cB * cS, 256>>>(feats, kpos, 1, ln_k_w, ln_k_b, p_nbuf);
    tf32_nt<128, 128><<<dim3(cD / 128, (cB * cS) / 128, 1), 256>>>(
        p_nbuf, cD, wk, cD, p_k, cD, cD, 1.f, nullptr, nullptr, 1, 0, 0, 0, 0, 0, 0);

    // V path
    ln_kernel<<<cB * cS, 256>>>(feats, nullptr, 0, ln_v_w, ln_v_b, p_nbuf);
    tf32_nt<128, 128><<<dim3(cD / 128, (cB * cS) / 128, 1), 256>>>(
        p_nbuf, cD, wv, cD, p_v, cD, cD, 1.f, nullptr, nullptr, 1, 0, 0, 0, 0, 0, 0);

    // Scores: attn[b,n,g,s] = 0.125 * q . k   (batched over z = b*G + g)
    tf32_nt<128, 128><<<dim3(cS / 128, cN / 128, cB * cG), 256>>>(
        p_q, cD, p_k, cD, out_attn, (long)cG * cS, cC, 0.125f, nullptr, nullptr,
        cG,
        (long)cN * cD, (long)cC,
        (long)cS * cD, (long)cC,
        (long)cN * cG * cS, (long)cS);

    softmax_kernel<<<cB * cN * cG, 256>>>(out_attn, p_mask);

    // AV: ao[b,n,g,c] = attn[b,n,g,:] @ v[b,:,g,c]   (NN, K = S)
    tf32_nn<<<dim3(cC / 64, cN / 64, cB * cG), 256>>>(
        out_attn, (long)cG * cS, p_v, cD, p_ao, cD, cS, nullptr,
        cG,
        (long)cN * cG * cS, (long)cS,
        (long)cS * cD, (long)cC,
        (long)cN * cD, (long)cC);

    // Projection + residual (M = 1024)
    tf32_nt<64, 64><<<dim3(cD / 64, (cB * cN) / 64, 1), 256>>>(
        p_ao, cD, w_proj, cD, p_p1, cD, cD, 1.f, b_proj, parts, 1, 0, 0, 0, 0, 0, 0);

    // Reason block: p2 = p1 + reason_w @ LN(p1)
    ln_kernel<<<cB * cN, 256>>>(p_p1, nullptr, 0, reason_ln_w, reason_ln_b, p_t);
    tf32_nn<<<dim3(cD / 64, cN / 64, cB), 256>>>(
        reason_w, cN, p_t, cD, p_p2, cD, cN, p_p1,
        1,
        0, 0,
        (long)cN * cD, 0,
        (long)cN * cD, 0);

    // MLP
    ln_kernel<<<cB * cN, 256>>>(p_p2, nullptr, 0, mlp_ln_w, mlp_ln_b, p_t);
    tf32_nt<64, 64><<<dim3(cD / 64, (cB * cN) / 64, 1), 256>>>(
        p_t, cD, fc1_w, cD, p_h, cD, cD, 1.f, fc1_b, nullptr, 1, 0, 0, 0, 0, 0, 0);
    gelu_kernel<<<(cB * cN * cD + 255) / 256, 256>>>(p_h, cB * cN * cD);
    tf32_nt<64, 64><<<dim3(cD / 64, (cB * cN) / 64, 1), 256>>>(
        p_h, cD, fc2_w, cD, out_parts, cD, cD, 1.f, fc2_b, p_p2, 1, 0, 0, 0, 0, 0, 0);

    (void)in_sizes; (void)n_in; (void)out_size;
}

// round 7
// speedup vs baseline: 2.9462x; 1.1729x over previous
#include <cuda_runtime.h>
#include <math.h>
#include <stdint.h>

constexpr int cB = 4;
constexpr int cS = 4096;
constexpr int cN = 256;
constexpr int cD = 1024;
constexpr int cG = 16;
constexpr int cC = 64;

// ---------------------------------------------------------------------------
// Static device scratch
// ---------------------------------------------------------------------------
__device__ float g_nbuf[cB * cS * cD];
__device__ float g_k[cB * cS * cD];
__device__ float g_v[cB * cS * cD];
__device__ float g_nq[cB * cN * cD];
__device__ float g_q[cB * cN * cD];
__device__ float g_ao[cB * cN * cD];
__device__ float g_p1[cB * cN * cD];
__device__ float g_p2[cB * cN * cD];
__device__ float g_t[cB * cN * cD];
__device__ float g_h[cB * cN * cD];
__device__ float g_cwq[cD * cD];
__device__ float g_cwk[cD * cD];
__device__ float g_cwv[cD * cD];
__device__ float g_cwp[cD * cD];
__device__ float g_cw1[cD * cD];
__device__ float g_cw2[cD * cD];
__device__ float g_cwr[cN * cN];
__device__ int   g_mask[cB * cS];
__device__ int   g_flag[1];

// ---------------------------------------------------------------------------
// tf32 helpers
// ---------------------------------------------------------------------------
__device__ __forceinline__ uint32_t f2tf(float f) {
    uint32_t u;
    asm("cvt.rna.tf32.f32 %0, %1;" : "=r"(u) : "f"(f));
    return u;
}
__device__ __forceinline__ float roundtf(float f) { return __uint_as_float(f2tf(f)); }

__device__ __forceinline__ void mma8(float* c, const uint32_t* a, const uint32_t* b) {
    asm volatile(
        "mma.sync.aligned.m16n8k8.row.col.f32.tf32.tf32.f32 "
        "{%0,%1,%2,%3}, {%4,%5,%6,%7}, {%8,%9}, {%0,%1,%2,%3};"
        : "+f"(c[0]), "+f"(c[1]), "+f"(c[2]), "+f"(c[3])
        : "r"(a[0]), "r"(a[1]), "r"(a[2]), "r"(a[3]), "r"(b[0]), "r"(b[1]));
}

#define CP16(smem_u32, gptr) \
    asm volatile("cp.async.ca.shared.global [%0], [%1], 16;" :: "r"(smem_u32), "l"(gptr))
#define CP_COMMIT() asm volatile("cp.async.commit_group;")
#define CP_WAIT1()  asm volatile("cp.async.wait_group 1;")

// ---------------------------------------------------------------------------
// Mask handling
// ---------------------------------------------------------------------------
__global__ void detect_mask_kernel(const unsigned char* __restrict__ p, int* flag) {
    __shared__ int red[256];
    int t = threadIdx.x;
    int cnt = 0;
    for (int i = t; i < cB * cS; i += 256)
        if ((i & 3) != 0 && p[i] != 0) cnt++;
    red[t] = cnt;
    __syncthreads();
    for (int s = 128; s > 0; s >>= 1) {
        if (t < s) red[t] += red[t + s];
        __syncthreads();
    }
    if (t == 0) flag[0] = red[0];
}

__global__ void expand_mask_kernel(const void* __restrict__ p, const int* __restrict__ flag,
                                   int* __restrict__ mout) {
    int i = blockIdx.x * 256 + threadIdx.x;
    if (i >= cB * cS) return;
    int isbyte = flag[0] > 0;
    int v = isbyte ? (int)((const unsigned char*)p)[i] : ((const int*)p)[i];
    mout[i] = (v != 0) ? 1 : 0;
}

// ---------------------------------------------------------------------------
// Preconvert fp32 -> tf32-rounded bits
// ---------------------------------------------------------------------------
__global__ void cvt_kernel(const float* __restrict__ s, float* __restrict__ d, int n) {
    int i = blockIdx.x * 256 + threadIdx.x;
    if (i < n) d[i] = roundtf(s[i]);
}

// ---------------------------------------------------------------------------
// LayerNorm over D=1024 (tf32-rounded output; all consumers are GEMMs)
// ---------------------------------------------------------------------------
__global__ void ln_kernel(const float* __restrict__ x, const float* __restrict__ add,
                          int addmode, const float* __restrict__ w, const float* __restrict__ bias,
                          float* __restrict__ out) {
    __shared__ float row[cD];
    __shared__ float red[256];
    int r = blockIdx.x;
    int t = threadIdx.x;
    const float* xr = x + (size_t)r * cD;

    float lsum = 0.f;
    for (int i = t; i < cD; i += 256) {
        float v = xr[i];
        if (addmode == 1)      v += add[(size_t)r * cD + i];
        else if (addmode == 2) v += add[(size_t)r * cC + (i & (cC - 1))];
        row[i] = v;
        lsum += v;
    }
    red[t] = lsum;
    __syncthreads();
    for (int s = 128; s > 0; s >>= 1) {
        if (t < s) red[t] += red[t + s];
        __syncthreads();
    }
    float mu = red[0] * (1.f / cD);
    __syncthreads();
    float lvar = 0.f;
    for (int i = t; i < cD; i += 256) {
        float d = row[i] - mu;
        lvar += d * d;
    }
    red[t] = lvar;
    __syncthreads();
    for (int s = 128; s > 0; s >>= 1) {
        if (t < s) red[t] += red[t + s];
        __syncthreads();
    }
    float inv = rsqrtf(red[0] * (1.f / cD) + 1e-5f);
    for (int i = t; i < cD; i += 256)
        out[(size_t)r * cD + i] = roundtf((row[i] - mu) * inv * w[i] + bias[i]);
}

// ---------------------------------------------------------------------------
// TF32 NT GEMM, cp.async 2-stage, 4 warps (WMxWN=2x2), warp tile (BM/2)x(BN/2).
// Inputs must already be tf32-rounded. C = alpha*A@W^T (+bias)(+resid).
// smem row stride 36 floats (144B: 16B-aligned, conflict-free fragments).
// ---------------------------------------------------------------------------
template <int BM, int BN>
__global__ void __launch_bounds__(128) tf32_nt(
    const float* __restrict__ A, long lda,
    const float* __restrict__ Bw, long ldb,
    float* __restrict__ Cp, long ldc,
    int K, float alpha,
    const float* __restrict__ bias, const float* __restrict__ resid, int round_out,
    int zdiv, long a1, long a2, long b1, long b2, long c1, long c2) {
    constexpr int T = 128;
    constexpr int WM = 2, WN = 2;
    constexpr int MT = BM / (16 * WM);
    constexpr int NT = BN / (8 * WN);
    constexpr int LDS = 36;
    constexpr int ASZ = BM * LDS;
    constexpr int BSZ = BN * LDS;
    constexpr int CA = BM * 4 / T;
    constexpr int CB = BN * 4 / T;

    extern __shared__ float smem[];
    float* As = smem;
    float* Bs = smem + 2 * ASZ;
    uint32_t as_u = (uint32_t)__cvta_generic_to_shared(As);
    uint32_t bs_u = (uint32_t)__cvta_generic_to_shared(Bs);

    int t = threadIdx.x, lane = t & 31, warp = t >> 5;
    int z = blockIdx.z, zo = z / zdiv, zi = z - zo * zdiv;
    const float* Ab = A + zo * a1 + zi * a2 + (long)blockIdx.y * BM * lda;
    const float* Bb = Bw + zo * b1 + zi * b2 + (long)blockIdx.x * BN * ldb;

    int wm0 = (warp & 1) * (16 * MT);
    int wn0 = (warp >> 1) * (8 * NT);
    int nslab = K >> 4;

    float acc[MT][NT][4];
#pragma unroll
    for (int i = 0; i < MT; i++)
#pragma unroll
        for (int j = 0; j < NT; j++)
#pragma unroll
            for (int e = 0; e < 4; e++) acc[i][j][e] = 0.f;

    auto issue = [&](int s) {
        if (s < nslab) {
            long k0 = (long)s * 16;
            int st = s & 1;
#pragma unroll
            for (int i = 0; i < CA; i++) {
                int q = t + i * T;
                int row = q >> 2, c4 = (q & 3) * 4;
                CP16(as_u + (uint32_t)(st * ASZ + row * LDS + c4) * 4,
                     Ab + (long)row * lda + k0 + c4);
            }
#pragma unroll
            for (int i = 0; i < CB; i++) {
                int q = t + i * T;
                int row = q >> 2, c4 = (q & 3) * 4;
                CP16(bs_u + (uint32_t)(st * BSZ + row * LDS + c4) * 4,
                     Bb + (long)row * ldb + k0 + c4);
            }
        }
        CP_COMMIT();
    };

    issue(0);
    issue(1);

    int r0 = wm0 + (lane >> 2);
    int n0 = wn0 + (lane >> 2);
    int kc0 = lane & 3;

    for (int s = 0; s < nslab; s++) {
        CP_WAIT1();
        __syncthreads();
        const float* as = As + (s & 1) * ASZ;
        const float* bs = Bs + (s & 1) * BSZ;
#pragma unroll
        for (int kq = 0; kq < 2; kq++) {
            int kc = kq * 8 + kc0;
            uint32_t af[MT][4], bf[NT][2];
#pragma unroll
            for (int i = 0; i < MT; i++) {
                int base = (r0 + i * 16) * LDS + kc;
                af[i][0] = __float_as_uint(as[base]);
                af[i][1] = __float_as_uint(as[base + 8 * LDS]);
                af[i][2] = __float_as_uint(as[base + 4]);
                af[i][3] = __float_as_uint(as[base + 8 * LDS + 4]);
            }
#pragma unroll
            for (int j = 0; j < NT; j++) {
                int base = (n0 + j * 8) * LDS + kc;
                bf[j][0] = __float_as_uint(bs[base]);
                bf[j][1] = __float_as_uint(bs[base + 4]);
            }
#pragma unroll
            for (int i = 0; i < MT; i++)
#pragma unroll
                for (int j = 0; j < NT; j++) mma8(acc[i][j], af[i], bf[j]);
        }
        __syncthreads();
        issue(s + 2);
    }

    float* Cb = Cp + zo * c1 + zi * c2;
    const float* Rb = resid ? (resid + zo * c1 + zi * c2) : (const float*)nullptr;
    long ccol0 = (long)blockIdx.x * BN + wn0;
#pragma unroll
    for (int i = 0; i < MT; i++) {
#pragma unroll
        for (int half = 0; half < 2; half++) {
            long row = (long)blockIdx.y * BM + wm0 + i * 16 + (lane >> 2) + half * 8;
#pragma unroll
            for (int j = 0; j < NT; j++) {
                long col = ccol0 + j * 8 + 2 * (lane & 3);
                float2 o;
                o.x = acc[i][j][half * 2 + 0] * alpha;
                o.y = acc[i][j][half * 2 + 1] * alpha;
                if (bias) { o.x += bias[col]; o.y += bias[col + 1]; }
                long off = row * ldc + col;
                if (Rb) {
                    float2 rv = *(const float2*)&Rb[off];
                    o.x += rv.x; o.y += rv.y;
                }
                if (round_out) { o.x = roundtf(o.x); o.y = roundtf(o.y); }
                *(float2*)&Cb[off] = o;
            }
        }
    }
}

// ---------------------------------------------------------------------------
// TF32 NN GEMM, cp.async 2-stage, 4 warps, BM=128, BN=64, warp tile 64x32.
// Inputs must already be tf32-rounded. C = A@B (+resid).
// ---------------------------------------------------------------------------
__global__ void __launch_bounds__(128) tf32_nn(
    const float* __restrict__ A, long lda,
    const float* __restrict__ Bm, long ldb,
    float* __restrict__ Cp, long ldc,
    int K,
    const float* __restrict__ resid, int round_out,
    int zdiv, long a1, long a2, long b1, long b2, long c1, long c2) {
    constexpr int T = 128;
    constexpr int BM = 128, BN = 64;
    constexpr int MT = 4, NT = 4;           // warp tile 64x32, warps 2x2
    constexpr int LDS = 36;
    constexpr int LDB_S = BN + 8;           // 72
    constexpr int ASZ = BM * LDS;
    constexpr int BSZ = 16 * LDB_S;
    constexpr int CA = BM * 4 / T;          // 4
    constexpr int CB = 16 * BN / 4 / T;     // 2

    extern __shared__ float smem[];
    float* As = smem;
    float* Bs = smem + 2 * ASZ;
    uint32_t as_u = (uint32_t)__cvta_generic_to_shared(As);
    uint32_t bs_u = (uint32_t)__cvta_generic_to_shared(Bs);

    int t = threadIdx.x, lane = t & 31, warp = t >> 5;
    int z = blockIdx.z, zo = z / zdiv, zi = z - zo * zdiv;
    const float* Ab = A + zo * a1 + zi * a2 + (long)blockIdx.y * BM * lda;
    const float* Bb = Bm + zo * b1 + zi * b2 + (long)blockIdx.x * BN;

    int wm0 = (warp & 1) * 64;
    int wn0 = (warp >> 1) * 32;
    int nslab = K >> 4;

    float acc[MT][NT][4];
#pragma unroll
    for (int i = 0; i < MT; i++)
#pragma unroll
        for (int j = 0; j < NT; j++)
#pragma unroll
            for (int e = 0; e < 4; e++) acc[i][j][e] = 0.f;

    auto issue = [&](int s) {
        if (s < nslab) {
            long k0 = (long)s * 16;
            int st = s & 1;
#pragma unroll
            for (int i = 0; i < CA; i++) {
                int q = t + i * T;
                int row = q >> 2, c4 = (q & 3) * 4;
                CP16(as_u + (uint32_t)(st * ASZ + row * LDS + c4) * 4,
                     Ab + (long)row * lda + k0 + c4);
            }
#pragma unroll
            for (int i = 0; i < CB; i++) {
                int q = t + i * T;
                int row = q >> 4, c4 = (q & 15) * 4;
                CP16(bs_u + (uint32_t)(st * BSZ + row * LDB_S + c4) * 4,
                     Bb + (k0 + row) * ldb + c4);
            }
        }
        CP_COMMIT();
    };

    issue(0);
    issue(1);

    int r0 = wm0 + (lane >> 2);
    int nb0 = wn0 + (lane >> 2);
    int kc0 = lane & 3;

    for (int s = 0; s < nslab; s++) {
        CP_WAIT1();
        __syncthreads();
        const float* as = As + (s & 1) * ASZ;
        const float* bs = Bs + (s & 1) * BSZ;
#pragma unroll
        for (int kq = 0; kq < 2; kq++) {
            int kc = kq * 8 + kc0;
            uint32_t af[MT][4], bf[NT][2];
#pragma unroll
            for (int i = 0; i < MT; i++) {
                int base = (r0 + i * 16) * LDS + kc;
                af[i][0] = __float_as_uint(as[base]);
                af[i][1] = __float_as_uint(as[base + 8 * LDS]);
                af[i][2] = __float_as_uint(as[base + 4]);
                af[i][3] = __float_as_uint(as[base + 8 * LDS + 4]);
            }
#pragma unroll
            for (int j = 0; j < NT; j++) {
                int nn = nb0 + j * 8;
                bf[j][0] = __float_as_uint(bs[kc * LDB_S + nn]);
                bf[j][1] = __float_as_uint(bs[(kc + 4) * LDB_S + nn]);
            }
#pragma unroll
            for (int i = 0; i < MT; i++)
#pragma unroll
                for (int j = 0; j < NT; j++) mma8(acc[i][j], af[i], bf[j]);
        }
        __syncthreads();
        issue(s + 2);
    }

    float* Cb = Cp + zo * c1 + zi * c2;
    const float* Rb = resid ? (resid + zo * c1 + zi * c2) : (const float*)nullptr;
    long ccol0 = (long)blockIdx.x * BN + wn0;
#pragma unroll
    for (int i = 0; i < MT; i++) {
#pragma unroll
        for (int half = 0; half < 2; half++) {
            long row = (long)blockIdx.y * BM + wm0 + i * 16 + (lane >> 2) + half * 8;
#pragma unroll
            for (int j = 0; j < NT; j++) {
                long col = ccol0 + j * 8 + 2 * (lane & 3);
                float2 o;
                o.x = acc[i][j][half * 2 + 0];
                o.y = acc[i][j][half * 2 + 1];
                long off = row * ldc + col;
                if (Rb) {
                    float2 rv = *(const float2*)&Rb[off];
                    o.x += rv.x; o.y += rv.y;
                }
                if (round_out) { o.x = roundtf(o.x); o.y = roundtf(o.y); }
                *(float2*)&Cb[off] = o;
            }
        }
    }
}

// ---------------------------------------------------------------------------
// Masked softmax, in place, writes tf32-rounded probabilities.
// ---------------------------------------------------------------------------
__global__ void softmax_kernel(float* __restrict__ attn, const int* __restrict__ mask) {
    __shared__ float red[256];
    int r = blockIdx.x;
    int t = threadIdx.x;
    int b = r / (cN * cG);
    float* rowp = attn + (size_t)r * cS;
    const int* mrow = mask + b * cS;

    float vals[16];
    int msk[16];
    float mx = -INFINITY;
#pragma unroll
    for (int i = 0; i < 16; i++) {
        int s = t + i * 256;
        msk[i] = mrow[s];
        vals[i] = rowp[s];
        if (!msk[i]) mx = fmaxf(mx, vals[i]);
    }
    red[t] = mx;
    __syncthreads();
    for (int s = 128; s > 0; s >>= 1) {
        if (t < s) red[t] = fmaxf(red[t], red[t + s]);
        __syncthreads();
    }
    mx = red[0];
    __syncthreads();
    float sum = 0.f;
#pragma unroll
    for (int i = 0; i < 16; i++) {
        float e = msk[i] ? 0.f : __expf(vals[i] - mx);
        vals[i] = e;
        sum += e;
    }
    red[t] = sum;
    __syncthreads();
    for (int s = 128; s > 0; s >>= 1) {
        if (t < s) red[t] += red[t + s];
        __syncthreads();
    }
    float inv = (red[0] > 0.f) ? 1.f / red[0] : 0.f;
#pragma unroll
    for (int i = 0; i < 16; i++)
        rowp[t + i * 256] = roundtf(vals[i] * inv);
}

// ---------------------------------------------------------------------------
// Exact GELU, writes tf32-rounded (feeds fc2 GEMM)
// ---------------------------------------------------------------------------
__global__ void gelu_kernel(float* __restrict__ x, int n) {
    int i = blockIdx.x * 256 + threadIdx.x;
    if (i >= n) return;
    float v = x[i];
    x[i] = roundtf(0.5f * v * (1.f + erff(v * 0.70710678118654752f)));
}

// ---------------------------------------------------------------------------
// Host launcher
// ---------------------------------------------------------------------------
extern "C" void kernel_launch(void* const* d_in, const int* in_sizes, int n_in,
                              void* d_out, int out_size) {
    const float* feats   = (const float*)d_in[0];
    const float* parts   = (const float*)d_in[1];
    const float* qpos    = (const float*)d_in[2];
    const float* kpos    = (const float*)d_in[3];
    const void*  maskraw = d_in[4];
    const float* ln_q_w  = (const float*)d_in[5];
    const float* ln_q_b  = (const float*)d_in[6];
    const float* ln_k_w  = (const float*)d_in[7];
    const float* ln_k_b  = (const float*)d_in[8];
    const float* ln_v_w  = (const float*)d_in[9];
    const float* ln_v_b  = (const float*)d_in[10];
    const float* wq      = (const float*)d_in[11];
    const float* wk      = (const float*)d_in[12];
    const float* wv      = (const float*)d_in[13];
    const float* w_proj  = (const float*)d_in[14];
    const float* b_proj  = (const float*)d_in[15];
    const float* reason_ln_w = (const float*)d_in[16];
    const float* reason_ln_b = (const float*)d_in[17];
    const float* reason_w    = (const float*)d_in[18];
    const float* mlp_ln_w    = (const float*)d_in[19];
    const float* mlp_ln_b    = (const float*)d_in[20];
    const float* fc1_w   = (const float*)d_in[21];
    const float* fc1_b   = (const float*)d_in[22];
    const float* fc2_w   = (const float*)d_in[23];
    const float* fc2_b   = (const float*)d_in[24];

    float* out_parts = (float*)d_out;
    float* out_attn  = out_parts + (size_t)cB * cN * cD;

    float *p_nbuf, *p_k, *p_v, *p_nq, *p_q, *p_ao, *p_p1, *p_p2, *p_t, *p_h;
    float *p_cwq, *p_cwk, *p_cwv, *p_cwp, *p_cw1, *p_cw2, *p_cwr;
    int *p_mask, *p_flag;
    cudaGetSymbolAddress((void**)&p_nbuf, g_nbuf);
    cudaGetSymbolAddress((void**)&p_k, g_k);
    cudaGetSymbolAddress((void**)&p_v, g_v);
    cudaGetSymbolAddress((void**)&p_nq, g_nq);
    cudaGetSymbolAddress((void**)&p_q, g_q);
    cudaGetSymbolAddress((void**)&p_ao, g_ao);
    cudaGetSymbolAddress((void**)&p_p1, g_p1);
    cudaGetSymbolAddress((void**)&p_p2, g_p2);
    cudaGetSymbolAddress((void**)&p_t, g_t);
    cudaGetSymbolAddress((void**)&p_h, g_h);
    cudaGetSymbolAddress((void**)&p_cwq, g_cwq);
    cudaGetSymbolAddress((void**)&p_cwk, g_cwk);
    cudaGetSymbolAddress((void**)&p_cwv, g_cwv);
    cudaGetSymbolAddress((void**)&p_cwp, g_cwp);
    cudaGetSymbolAddress((void**)&p_cw1, g_cw1);
    cudaGetSymbolAddress((void**)&p_cw2, g_cw2);
    cudaGetSymbolAddress((void**)&p_cwr, g_cwr);
    cudaGetSymbolAddress((void**)&p_mask, g_mask);
    cudaGetSymbolAddress((void**)&p_flag, g_flag);

    // Raise dynamic smem limit for the big NT instantiation (72KB)
    cudaFuncSetAttribute(tf32_nt<128, 128>, cudaFuncAttributeMaxDynamicSharedMemorySize, 73728);
    const int SM_BIG   = 2 * (128 + 128) * 36 * 4;   // 73728
    const int SM_SMALL = 2 * (64 + 64) * 36 * 4;     // 36864
    const int SM_NN    = (2 * 128 * 36 + 2 * 16 * 72) * 4;  // 46080

    detect_mask_kernel<<<1, 256>>>((const unsigned char*)maskraw, p_flag);
    expand_mask_kernel<<<(cB * cS + 255) / 256, 256>>>(maskraw, p_flag, p_mask);

    // Preconvert weights to tf32
    int nw = cD * cD;
    cvt_kernel<<<(nw + 255) / 256, 256>>>(wq, p_cwq, nw);
    cvt_kernel<<<(nw + 255) / 256, 256>>>(wk, p_cwk, nw);
    cvt_kernel<<<(nw + 255) / 256, 256>>>(wv, p_cwv, nw);
    cvt_kernel<<<(nw + 255) / 256, 256>>>(w_proj, p_cwp, nw);
    cvt_kernel<<<(nw + 255) / 256, 256>>>(fc1_w, p_cw1, nw);
    cvt_kernel<<<(nw + 255) / 256, 256>>>(fc2_w, p_cw2, nw);
    cvt_kernel<<<(cN * cN + 255) / 256, 256>>>(reason_w, p_cwr, cN * cN);

    // Q path
    ln_kernel<<<cB * cN, 256>>>(parts, qpos, 2, ln_q_w, ln_q_b, p_nq);
    tf32_nt<64, 64><<<dim3(16, 16, 1), 128, SM_SMALL>>>(
        p_nq, cD, p_cwq, cD, p_q, cD, cD, 1.f, nullptr, nullptr, 1,
        1, 0, 0, 0, 0, 0, 0);

    // K path
    ln_kernel<<<cB * cS, 256>>>(feats, kpos, 1, ln_k_w, ln_k_b, p_nbuf);
    tf32_nt<128, 128><<<dim3(8, 128, 1), 128, SM_BIG>>>(
        p_nbuf, cD, p_cwk, cD, p_k, cD, cD, 1.f, nullptr, nullptr, 1,
        1, 0, 0, 0, 0, 0, 0);

    // V path
    ln_kernel<<<cB * cS, 256>>>(feats, nullptr, 0, ln_v_w, ln_v_b, p_nbuf);
    tf32_nt<128, 128><<<dim3(8, 128, 1), 128, SM_BIG>>>(
        p_nbuf, cD, p_cwv, cD, p_v, cD, cD, 1.f, nullptr, nullptr, 1,
        1, 0, 0, 0, 0, 0, 0);

    // Scores (logits, fp32; softmax rounds)
    tf32_nt<128, 128><<<dim3(32, 2, cB * cG), 128, SM_BIG>>>(
        p_q, cD, p_k, cD, out_attn, (long)cG * cS, cC, 0.125f, nullptr, nullptr, 0,
        cG,
        (long)cN * cD, (long)cC,
        (long)cS * cD, (long)cC,
        (long)cN * cG * cS, (long)cS);

    softmax_kernel<<<cB * cN * cG, 256>>>(out_attn, p_mask);

    // AV: ao[b,n,g,:] = attn[b,n,g,:] @ v[b,:,g,:]
    tf32_nn<<<dim3(1, 2, cB * cG), 128, SM_NN>>>(
        out_attn, (long)cG * cS, p_v, cD, p_ao, cD, cS, nullptr, 1,
        cG,
        (long)cN * cG * cS, (long)cS,
        (long)cS * cD, (long)cC,
        (long)cN * cD, (long)cC);

    // Projection + residual
    tf32_nt<64, 64><<<dim3(16, 16, 1), 128, SM_SMALL>>>(
        p_ao, cD, p_cwp, cD, p_p1, cD, cD, 1.f, b_proj, parts, 0,
        1, 0, 0, 0, 0, 0, 0);

    // Reason block: p2 = p1 + reason_w @ LN(p1)
    ln_kernel<<<cB * cN, 256>>>(p_p1, nullptr, 0, reason_ln_w, reason_ln_b, p_t);
    tf32_nn<<<dim3(16, 2, cB), 128, SM_NN>>>(
        p_cwr, cN, p_t, cD, p_p2, cD, cN, p_p1, 0,
        1,
        0, 0,
        (long)cN * cD, 0,
        (long)cN * cD, 0);

    // MLP
    ln_kernel<<<cB * cN, 256>>>(p_p2, nullptr, 0, mlp_ln_w, mlp_ln_b, p_t);
    tf32_nt<64, 64><<<dim3(16, 16, 1), 128, SM_SMALL>>>(
        p_t, cD, p_cw1, cD, p_h, cD, cD, 1.f, fc1_b, nullptr, 0,
        1, 0, 0, 0, 0, 0, 0);
    gelu_kernel<<<(cB * cN * cD + 255) / 256, 256>>>(p_h, cB * cN * cD);
    tf32_nt<64, 64><<<dim3(16, 16, 1), 128, SM_SMALL>>>(
        p_h, cD, p_cw2, cD, out_parts, cD, cD, 1.f, fc2_b, p_p2, 0,
        1, 0, 0, 0, 0, 0, 0);

    (void)in_sizes; (void)n_in; (void)out_size;
}